// round 9
// baseline (speedup 1.0000x reference)
#include <cuda_runtime.h>
#include <cuda_bf16.h>
#include <cstdint>

// ---------------- constants ----------------
#define HN     256
#define WN     256
#define HPAD   258
#define WPAD   258
#define NPTS   100000
#define BATCH  4
#define TOTPTS 400000
#define PLANE_PAD (HPAD*WPAD)                        // 66564
#define GRID_ELEMS ((size_t)BATCH*64*HPAD*WPAD)      // 17,040,384

// ---------------- device scratch ----------------
__device__ float g_bev[GRID_ELEMS];                  // fp32 NCHW padded (scatter target)
__device__ __nv_bfloat16 g_c1h[GRID_ELEMS];          // conv1 input NHWC padded, hi
__device__ __nv_bfloat16 g_c1l[GRID_ELEMS];          // lo
__device__ __nv_bfloat16 g_c2h[GRID_ELEMS];          // conv2 input NHWC padded, hi
__device__ __nv_bfloat16 g_c2l[GRID_ELEMS];          // lo
__device__ __nv_bfloat16 g_cw1h[9*64*64];            // [tap][co][ci] bf16 hi, BN-folded
__device__ __nv_bfloat16 g_cw1l[9*64*64];
__device__ __nv_bfloat16 g_cw2h[9*64*64];
__device__ __nv_bfloat16 g_cw2l[9*64*64];
__device__ __nv_bfloat16 g_mw1h[2*64*64];            // MLP L1 W [panel][co][k] hi (k<128)
__device__ __nv_bfloat16 g_mw1l[2*64*64];
__device__ __nv_bfloat16 g_mw2h[64*64];              // MLP L2 W [co][c]
__device__ __nv_bfloat16 g_mw2l[64*64];
__device__ float g_w1p[3*64];                        // pos rows of W1 (BN-folded, fp32)
__device__ float g_fb1[64];
__device__ float g_cb1[64];
__device__ float g_cb2[64];

// ---------------- mma / ldmatrix / cp.async helpers ----------------
__device__ __forceinline__ uint32_t smem_u32(const void* p){
    uint32_t a;
    asm("{ .reg .u64 t; cvta.to.shared.u64 t, %1; cvt.u32.u64 %0, t; }"
        : "=r"(a) : "l"(p));
    return a;
}
#define LDSM_X4(r0,r1,r2,r3,addr) asm volatile( \
    "ldmatrix.sync.aligned.m8n8.x4.shared.b16 {%0,%1,%2,%3}, [%4];" \
    : "=r"(r0), "=r"(r1), "=r"(r2), "=r"(r3) : "r"(addr))
#define LDSM_X2(r0,r1,addr) asm volatile( \
    "ldmatrix.sync.aligned.m8n8.x2.shared.b16 {%0,%1}, [%2];" \
    : "=r"(r0), "=r"(r1) : "r"(addr))
#define MMA_BF16(c0,c1,c2,c3,a0,a1,a2,a3,b0,b1) asm volatile( \
    "mma.sync.aligned.m16n8k16.row.col.f32.bf16.bf16.f32 " \
    "{%0,%1,%2,%3}, {%4,%5,%6,%7}, {%8,%9}, {%0,%1,%2,%3};" \
    : "+f"(c0), "+f"(c1), "+f"(c2), "+f"(c3) \
    : "r"(a0), "r"(a1), "r"(a2), "r"(a3), "r"(b0), "r"(b1))
#define CP16(dst, src) asm volatile( \
    "cp.async.cg.shared.global [%0], [%1], 16;" :: "r"(dst), "l"(src))
#define CP_COMMIT() asm volatile("cp.async.commit_group;" ::: "memory")
#define CP_WAIT(n)  asm volatile("cp.async.wait_group %0;" :: "n"(n) : "memory")

// ---------------- init: zero BEV grid + fold weights (one launch) ----------------
#define ZBLOCKS 16641    // ceil(GRID_ELEMS/4 / 256)
#define PREP_TOTAL (8192 + 4096 + 192 + 64 + 2*9*64*64 + 2*64)

__global__ void init_kernel(
    const float* __restrict__ w1, const float* __restrict__ b1,
    const float* __restrict__ g1, const float* __restrict__ be1,
    const float* __restrict__ m1, const float* __restrict__ v1,
    const float* __restrict__ w2,
    const float* __restrict__ cw1, const float* __restrict__ cb1,
    const float* __restrict__ cg1, const float* __restrict__ cbe1,
    const float* __restrict__ cm1, const float* __restrict__ cv1,
    const float* __restrict__ cw2, const float* __restrict__ cb2,
    const float* __restrict__ cg2, const float* __restrict__ cbe2,
    const float* __restrict__ cm2, const float* __restrict__ cv2)
{
    if (blockIdx.x < ZBLOCKS){
        size_t i = (size_t)blockIdx.x*256 + threadIdx.x;
        if (i < GRID_ELEMS/4)
            ((float4*)g_bev)[i] = make_float4(0.f,0.f,0.f,0.f);
        return;
    }
    int idx = (blockIdx.x - ZBLOCKS)*256 + threadIdx.x;
    if (idx >= PREP_TOTAL) return;
    if (idx < 8192){                      // MLP W1 k<128: [panel][co][kk]
        int p = idx >> 12, r = idx & 4095, co = r >> 6, kk = r & 63;
        int k = p*64 + kk;
        float s = g1[co]*rsqrtf(v1[co]+1e-5f);
        float wf = w1[k*64+co]*s;
        __nv_bfloat16 hi = __float2bfloat16(wf);
        g_mw1h[idx] = hi;
        g_mw1l[idx] = __float2bfloat16(wf - __bfloat162float(hi));
        return;
    }
    idx -= 8192;
    if (idx < 4096){                      // MLP W2: [co][c]
        int co = idx >> 6, c = idx & 63;
        float wf = w2[c*64+co];
        __nv_bfloat16 hi = __float2bfloat16(wf);
        g_mw2h[idx] = hi;
        g_mw2l[idx] = __float2bfloat16(wf - __bfloat162float(hi));
        return;
    }
    idx -= 4096;
    if (idx < 192){                       // pos rows of W1, fp32
        int i = idx >> 6, co = idx & 63;
        float s = g1[co]*rsqrtf(v1[co]+1e-5f);
        g_w1p[idx] = w1[(128+i)*64+co]*s;
        return;
    }
    idx -= 192;
    if (idx < 64){
        float s = g1[idx]*rsqrtf(v1[idx]+1e-5f);
        g_fb1[idx] = (b1[idx]-m1[idx])*s + be1[idx];
        return;
    }
    idx -= 64;
    if (idx < 9*64*64){
        int t = idx >> 12, co = (idx >> 6) & 63, ci = idx & 63;
        float s = cg1[co]*rsqrtf(cv1[co]+1e-5f);
        float wf = cw1[(co*64+ci)*9 + t]*s;
        __nv_bfloat16 hi = __float2bfloat16(wf);
        g_cw1h[idx] = hi;
        g_cw1l[idx] = __float2bfloat16(wf - __bfloat162float(hi));
        return;
    }
    idx -= 9*64*64;
    if (idx < 9*64*64){
        int t = idx >> 12, co = (idx >> 6) & 63, ci = idx & 63;
        float s = cg2[co]*rsqrtf(cv2[co]+1e-5f);
        float wf = cw2[(co*64+ci)*9 + t]*s;
        __nv_bfloat16 hi = __float2bfloat16(wf);
        g_cw2h[idx] = hi;
        g_cw2l[idx] = __float2bfloat16(wf - __bfloat162float(hi));
        return;
    }
    idx -= 9*64*64;
    if (idx < 64){
        float s = cg1[idx]*rsqrtf(cv1[idx]+1e-5f);
        g_cb1[idx] = (cb1[idx]-cm1[idx])*s + cbe1[idx];
        return;
    }
    idx -= 64;
    if (idx < 64){
        float s = cg2[idx]*rsqrtf(cv2[idx]+1e-5f);
        g_cb2[idx] = (cb2[idx]-cm2[idx])*s + cbe2[idx];
    }
}

// ---------------- tensor-core MLP + scatter-max (R8, unchanged) ----------------
#define MLPS_W1   0
#define MLPS_W2   32768
#define MLPS_A    49152
#define MLPS_HH   81920
#define MLPS_HL   90112
#define MLPS_W1P  98304
#define MLPS_FB1  99072
#define MLPS_B2   99328
#define MLPS_POS  99584
#define MLPS_INFO 100608
#define MLP_SMEM_BYTES 100864
#define NCHUNKS 6250

__global__ __launch_bounds__(256, 2)
void mlp_mma_kernel(const float* __restrict__ points,
                    const float* __restrict__ features,
                    const float* __restrict__ b2)
{
    extern __shared__ char smem[];
    uint32_t sb = smem_u32(smem);
    float* s_w1p = (float*)(smem + MLPS_W1P);
    float* s_fb1 = (float*)(smem + MLPS_FB1);
    float* s_b2  = (float*)(smem + MLPS_B2);
    float* s_pos = (float*)(smem + MLPS_POS);
    int*   s_info= (int*)(smem + MLPS_INFO);

    int tid = threadIdx.x;
    int lane = tid & 31;
    int wq = tid >> 5;
    int wm = wq & 3;
    int wn = wq >> 2;
    int tile = lane >> 3;
    int r16  = ((tile & 1) << 3) + (lane & 7);
    int kcA  = tile >> 1;
    int coL  = lane & 7;
    int kcB  = tile & 1;

    for (int j = tid; j < 2048; j += 256){
        int panel = j >> 9, r = (j >> 3) & 63, c = j & 7;
        const __nv_bfloat16* src = (panel < 2)
            ? (g_mw1h + panel*4096 + r*64 + c*8)
            : (g_mw1l + (panel-2)*4096 + r*64 + c*8);
        CP16(sb + MLPS_W1 + panel*8192 + r*128 + ((c ^ (r & 7)) << 4), src);
    }
    for (int j = tid; j < 1024; j += 256){
        int panel = j >> 9, r = (j >> 3) & 63, c = j & 7;
        const __nv_bfloat16* src = (panel ? g_mw2l : g_mw2h) + r*64 + c*8;
        CP16(sb + MLPS_W2 + panel*8192 + r*128 + ((c ^ (r & 7)) << 4), src);
    }
    CP_COMMIT();
    if (tid < 192) s_w1p[tid] = g_w1p[tid];
    if (tid < 64){ s_fb1[tid] = g_fb1[tid]; s_b2[tid] = b2[tid]; }
    CP_WAIT(0);
    __syncthreads();

    for (int chunk = blockIdx.x; chunk < NCHUNKS; chunk += gridDim.x){
        int g0 = chunk * 64;

        #pragma unroll
        for (int i = 0; i < 4; ++i){
            int j = tid + i*256;
            int pt = j >> 4, oct = j & 15;
            const uint4* src = (const uint4*)(features + (size_t)(g0+pt)*128 + oct*8);
            uint4 u0 = src[0], u1 = src[1];
            uint4 hv, lv;
            hv.x = __byte_perm(u0.x, u0.y, 0x7632);
            hv.y = __byte_perm(u0.z, u0.w, 0x7632);
            hv.z = __byte_perm(u1.x, u1.y, 0x7632);
            hv.w = __byte_perm(u1.z, u1.w, 0x7632);
            float l0 = __uint_as_float(u0.x) - __uint_as_float(u0.x & 0xFFFF0000u);
            float l1 = __uint_as_float(u0.y) - __uint_as_float(u0.y & 0xFFFF0000u);
            float l2 = __uint_as_float(u0.z) - __uint_as_float(u0.z & 0xFFFF0000u);
            float l3 = __uint_as_float(u0.w) - __uint_as_float(u0.w & 0xFFFF0000u);
            float l4 = __uint_as_float(u1.x) - __uint_as_float(u1.x & 0xFFFF0000u);
            float l5 = __uint_as_float(u1.y) - __uint_as_float(u1.y & 0xFFFF0000u);
            float l6 = __uint_as_float(u1.z) - __uint_as_float(u1.z & 0xFFFF0000u);
            float l7 = __uint_as_float(u1.w) - __uint_as_float(u1.w & 0xFFFF0000u);
            lv.x = __byte_perm(__float_as_uint(l0), __float_as_uint(l1), 0x7632);
            lv.y = __byte_perm(__float_as_uint(l2), __float_as_uint(l3), 0x7632);
            lv.z = __byte_perm(__float_as_uint(l4), __float_as_uint(l5), 0x7632);
            lv.w = __byte_perm(__float_as_uint(l6), __float_as_uint(l7), 0x7632);
            int panel = oct >> 3, c = oct & 7;
            uint32_t off = MLPS_A + panel*8192 + pt*128 + ((c ^ (pt & 7)) << 4);
            *(uint4*)(smem + off) = hv;
            *(uint4*)(smem + off + 16384) = lv;
        }
        if (tid < 64){
            int g = g0 + tid;
            float x = points[(size_t)g*3+0];
            float y = points[(size_t)g*3+1];
            float z = points[(size_t)g*3+2];
            bool valid = (x >= -50.f) && (x < 50.f) && (y >= -50.f) &&
                         (y < 50.f) && (z >= -3.f) && (z < 5.f);
            s_pos[tid*4+0] = __fdiv_rn(x + 50.f, 100.f);
            s_pos[tid*4+1] = __fdiv_rn(y + 50.f, 100.f);
            s_pos[tid*4+2] = __fdiv_rn(z + 3.f, 8.f);
            int info = -1;
            if (valid){
                int col = (int)__fdiv_rn(x + 50.f, 0.390625f);
                int row = (int)__fdiv_rn(y + 50.f, 0.390625f);
                col = min(max(col,0),255); row = min(max(row,0),255);
                int b = g / NPTS;
                info = (b<<18) | (row<<9) | col;
            }
            s_info[tid] = info;
        }
        __syncthreads();

        float acc[4][4];
        #pragma unroll
        for (int in = 0; in < 4; ++in)
            #pragma unroll
            for (int r = 0; r < 4; ++r) acc[in][r] = 0.f;

        int arow = 16*wm + r16;
        #pragma unroll
        for (int ks = 0; ks < 8; ++ks){
            int panel = ks >> 2, cc = 2*(ks & 3);
            uint32_t ah[4], al[4], bh[4][2], bl[4][2];
            uint32_t aad = sb + MLPS_A + panel*8192 + arow*128
                         + (((cc + kcA) ^ (arow & 7)) << 4);
            LDSM_X4(ah[0], ah[1], ah[2], ah[3], aad);
            LDSM_X4(al[0], al[1], al[2], al[3], aad + 16384);
            #pragma unroll
            for (int in = 0; in < 4; ++in){
                int co = 32*wn + 8*in + coL;
                uint32_t bad = sb + MLPS_W1 + panel*8192 + co*128
                             + (((cc + kcB) ^ (co & 7)) << 4);
                LDSM_X2(bh[in][0], bh[in][1], bad);
                LDSM_X2(bl[in][0], bl[in][1], bad + 16384);
            }
            #pragma unroll
            for (int in = 0; in < 4; ++in){
                MMA_BF16(acc[in][0],acc[in][1],acc[in][2],acc[in][3],
                         ah[0],ah[1],ah[2],ah[3], bh[in][0],bh[in][1]);
                MMA_BF16(acc[in][0],acc[in][1],acc[in][2],acc[in][3],
                         ah[0],ah[1],ah[2],ah[3], bl[in][0],bl[in][1]);
                MMA_BF16(acc[in][0],acc[in][1],acc[in][2],acc[in][3],
                         al[0],al[1],al[2],al[3], bh[in][0],bh[in][1]);
            }
        }

        int rb = 16*wm + (lane >> 2);
        int cb = 2*(lane & 3);
        #pragma unroll
        for (int in = 0; in < 4; ++in){
            int c0 = 32*wn + 8*in + cb;
            float p0a = s_w1p[c0],      p0b = s_w1p[c0+1];
            float p1a = s_w1p[64+c0],   p1b = s_w1p[64+c0+1];
            float p2a = s_w1p[128+c0],  p2b = s_w1p[128+c0+1];
            float fba = s_fb1[c0], fbb = s_fb1[c0+1];
            int ch = c0 >> 3;
            #pragma unroll
            for (int half = 0; half < 2; ++half){
                int pt = rb + 8*half;
                float px = s_pos[pt*4], py = s_pos[pt*4+1], pz = s_pos[pt*4+2];
                float v0 = acc[in][2*half]   + fba + px*p0a + py*p1a + pz*p2a;
                float v1 = acc[in][2*half+1] + fbb + px*p0b + py*p1b + pz*p2b;
                v0 = fmaxf(v0, 0.f); v1 = fmaxf(v1, 0.f);
                __nv_bfloat16 h0 = __float2bfloat16(v0);
                __nv_bfloat16 h1 = __float2bfloat16(v1);
                __nv_bfloat16 q0 = __float2bfloat16(v0 - __bfloat162float(h0));
                __nv_bfloat16 q1 = __float2bfloat16(v1 - __bfloat162float(h1));
                uint32_t hp = (uint32_t)__bfloat16_as_ushort(h0) |
                              ((uint32_t)__bfloat16_as_ushort(h1) << 16);
                uint32_t lp = (uint32_t)__bfloat16_as_ushort(q0) |
                              ((uint32_t)__bfloat16_as_ushort(q1) << 16);
                uint32_t off = pt*128 + ((ch ^ (pt & 7)) << 4) + cb*2;
                *(uint32_t*)(smem + MLPS_HH + off) = hp;
                *(uint32_t*)(smem + MLPS_HL + off) = lp;
            }
        }
        __syncthreads();

        float acc2[4][4];
        #pragma unroll
        for (int in = 0; in < 4; ++in)
            #pragma unroll
            for (int r = 0; r < 4; ++r) acc2[in][r] = 0.f;

        #pragma unroll
        for (int ks = 0; ks < 4; ++ks){
            int cc = 2*ks;
            uint32_t ah[4], al[4], bh[4][2], bl[4][2];
            uint32_t aad = sb + MLPS_HH + arow*128
                         + (((cc + kcA) ^ (arow & 7)) << 4);
            LDSM_X4(ah[0], ah[1], ah[2], ah[3], aad);
            LDSM_X4(al[0], al[1], al[2], al[3], aad + 8192);
            #pragma unroll
            for (int in = 0; in < 4; ++in){
                int co = 32*wn + 8*in + coL;
                uint32_t bad = sb + MLPS_W2 + co*128
                             + (((cc + kcB) ^ (co & 7)) << 4);
                LDSM_X2(bh[in][0], bh[in][1], bad);
                LDSM_X2(bl[in][0], bl[in][1], bad + 8192);
            }
            #pragma unroll
            for (int in = 0; in < 4; ++in){
                MMA_BF16(acc2[in][0],acc2[in][1],acc2[in][2],acc2[in][3],
                         ah[0],ah[1],ah[2],ah[3], bh[in][0],bh[in][1]);
                MMA_BF16(acc2[in][0],acc2[in][1],acc2[in][2],acc2[in][3],
                         ah[0],ah[1],ah[2],ah[3], bl[in][0],bl[in][1]);
                MMA_BF16(acc2[in][0],acc2[in][1],acc2[in][2],acc2[in][3],
                         al[0],al[1],al[2],al[3], bh[in][0],bh[in][1]);
            }
        }

        #pragma unroll
        for (int in = 0; in < 4; ++in){
            int c0 = 32*wn + 8*in + cb;
            float bb0 = s_b2[c0], bb1 = s_b2[c0+1];
            #pragma unroll
            for (int half = 0; half < 2; ++half){
                int pt = rb + 8*half;
                int info = s_info[pt];
                if (info < 0) continue;
                int b   = info >> 18;
                int row = (info >> 9) & 511;
                int col = info & 511;
                float v0 = acc2[in][2*half]   + bb0;
                float v1 = acc2[in][2*half+1] + bb1;
                size_t obase = ((size_t)(b*64 + c0)*HPAD + row + 1)*WPAD + col + 1;
                if (v0 > 0.f)
                    atomicMax((unsigned int*)&g_bev[obase], __float_as_uint(v0));
                if (v1 > 0.f)
                    atomicMax((unsigned int*)&g_bev[obase + PLANE_PAD],
                              __float_as_uint(v1));
            }
        }
        __syncthreads();
    }
}

// ---------------- bev fp32 NCHW -> NHWC bf16 hi/lo ----------------
__global__ __launch_bounds__(256)
void bev2bf16_kernel(){
    __shared__ float ts[64*65];
    int b = blockIdx.z, h = blockIdx.y, w0 = blockIdx.x*64;
    int tid = threadIdx.x;
    #pragma unroll
    for (int i = 0; i < 16; ++i){
        int idx = tid + i*256;
        int ch = idx >> 6, px = idx & 63;
        ts[ch*65 + px] = g_bev[(size_t)(b*64+ch)*PLANE_PAD
                               + (size_t)(h+1)*WPAD + (w0+1+px)];
    }
    __syncthreads();
    int px = tid >> 2, cq = (tid & 3) * 16;
    size_t base = (((size_t)b*HPAD + h + 1)*WPAD + (w0+1+px))*64 + cq;
    uint32_t hp[8], lp[8];
    #pragma unroll
    for (int j = 0; j < 8; ++j){
        float v0 = ts[(cq+2*j)*65 + px];
        float v1 = ts[(cq+2*j+1)*65 + px];
        __nv_bfloat16 h0 = __float2bfloat16(v0);
        __nv_bfloat16 h1 = __float2bfloat16(v1);
        __nv_bfloat16 l0 = __float2bfloat16(v0 - __bfloat162float(h0));
        __nv_bfloat16 l1 = __float2bfloat16(v1 - __bfloat162float(h1));
        hp[j] = (uint32_t)__bfloat16_as_ushort(h0) |
                ((uint32_t)__bfloat16_as_ushort(h1) << 16);
        lp[j] = (uint32_t)__bfloat16_as_ushort(l0) |
                ((uint32_t)__bfloat16_as_ushort(l1) << 16);
    }
    *(uint4*)(g_c1h + base)     = *(uint4*)&hp[0];
    *(uint4*)(g_c1h + base + 8) = *(uint4*)&hp[4];
    *(uint4*)(g_c1l + base)     = *(uint4*)&lp[0];
    *(uint4*)(g_c1l + base + 8) = *(uint4*)&lp[4];
}

// ---------------- conv via mma.sync: 2 output rows per CTA (M=256) ----------------
// 4 input strips (dh=0..3) staged ONCE per CTA; W double-buffered per tap.
// 8 warps: wm 0..3 -> M rows 64*wm (wm<2 = output row 0, wm>=2 = row 1), wn 0..1.
#define CS_STRIP 33280                 // per strip: hi 16640 + lo 16640 (130 px x 128B)
#define CS_W     (4*CS_STRIP)          // 133120
#define CS_WBUF  16384
#define CS_BIAS  (CS_W + 2*CS_WBUF)    // 165888
#define CONV_SMEM_BYTES (CS_BIAS + 256)

template<int MODE>
__global__ __launch_bounds__(256, 1)
void conv_mma_kernel(const __nv_bfloat16* __restrict__ in_h,
                     const __nv_bfloat16* __restrict__ in_l,
                     const __nv_bfloat16* __restrict__ w_h,
                     const __nv_bfloat16* __restrict__ w_l,
                     const float* __restrict__ bias,
                     __nv_bfloat16* __restrict__ out_h,
                     __nv_bfloat16* __restrict__ out_l,
                     float* __restrict__ out_f)
{
    extern __shared__ char smem[];
    uint32_t sbase = smem_u32(smem);
    float* s_bias = (float*)(smem + CS_BIAS);

    int tid = threadIdx.x;
    int lane = tid & 31;
    int wq = tid >> 5;
    int wm = wq & 3;
    int wn = wq >> 2;
    int b = blockIdx.z, h0 = blockIdx.y * 2, W0 = blockIdx.x * 128;

    if (tid < 64) s_bias[tid] = bias[tid];

    int tile = lane >> 3;
    int r16  = ((tile & 1) << 3) + (lane & 7);
    int kcA  = tile >> 1;
    int coL  = (lane & 7);
    int kcB  = tile & 1;

    // ---- stage all 4 strips (input rows h0..h0+3, padded coords) ----
    #pragma unroll 1
    for (int s = 0; s < 4; ++s){
        const char* srch = (const char*)(in_h +
            (((size_t)b*HPAD + h0 + s)*WPAD + W0)*64);
        const char* srcl = (const char*)(in_l +
            (((size_t)b*HPAD + h0 + s)*WPAD + W0)*64);
        uint32_t dsth = sbase + s*CS_STRIP;
        #pragma unroll 1
        for (int ch = tid; ch < 1040; ch += 256){
            int px = ch >> 3, c = ch & 7;
            uint32_t off = px*128 + ((c ^ (px & 7)) << 4);
            CP16(dsth + off, srch + ch*16);
            CP16(dsth + 16640 + off, srcl + ch*16);
        }
    }
    // ---- stage W tap 0 ----
    auto stage_w = [&](int t, int buf){
        const char* srch = (const char*)(w_h + t*4096);
        const char* srcl = (const char*)(w_l + t*4096);
        uint32_t dsth = sbase + CS_W + buf*CS_WBUF;
        uint32_t dstl = dsth + 8192;
        #pragma unroll 1
        for (int ch = tid; ch < 512; ch += 256){
            int co = ch >> 3, c = ch & 7;
            uint32_t off = co*128 + ((c ^ (co & 7)) << 4);
            CP16(dsth + off, srch + ch*16);
            CP16(dstl + off, srcl + ch*16);
        }
    };
    stage_w(0, 0);
    CP_COMMIT();

    float acc[4][4][4];
    #pragma unroll
    for (int im = 0; im < 4; ++im)
        #pragma unroll
        for (int in = 0; in < 4; ++in)
            #pragma unroll
            for (int r = 0; r < 4; ++r) acc[im][in][r] = 0.f;

    int strip_r = wm >> 1;               // 0 for warps 0,1 ; 1 for warps 2,3
    int pxw = 64*(wm & 1) + r16;         // px base within strip (per warp)

    #pragma unroll 1
    for (int t = 0; t < 9; ++t){
        int dh = t / 3, dw = t - dh*3;
        if (t < 8){
            stage_w(t+1, (t+1) & 1);
            CP_COMMIT();
            CP_WAIT(1);
        } else {
            CP_WAIT(0);
        }
        __syncthreads();

        uint32_t sA = sbase + (dh + strip_r)*CS_STRIP;
        uint32_t Wh = sbase + CS_W + (t & 1)*CS_WBUF;
        uint32_t Wl = Wh + 8192;

        #pragma unroll
        for (int ks = 0; ks < 4; ++ks){
            uint32_t ah[4][4], al[4][4], bh[4][2], bl[4][2];
            #pragma unroll
            for (int im = 0; im < 4; ++im){
                int px = dw + pxw + 16*im;
                int chunk = 2*ks + kcA;
                uint32_t ad = sA + px*128 + ((chunk ^ (px & 7)) << 4);
                LDSM_X4(ah[im][0], ah[im][1], ah[im][2], ah[im][3], ad);
                LDSM_X4(al[im][0], al[im][1], al[im][2], al[im][3], ad + 16640);
            }
            #pragma unroll
            for (int in = 0; in < 4; ++in){
                int co = 32*wn + 8*in + coL;
                int chunk = 2*ks + kcB;
                uint32_t bd = Wh + co*128 + ((chunk ^ (co & 7)) << 4);
                LDSM_X2(bh[in][0], bh[in][1], bd);
                LDSM_X2(bl[in][0], bl[in][1], bd + 8192);
            }
            #pragma unroll
            for (int im = 0; im < 4; ++im)
                #pragma unroll
                for (int in = 0; in < 4; ++in){
                    MMA_BF16(acc[im][in][0], acc[im][in][1],
                             acc[im][in][2], acc[im][in][3],
                             ah[im][0], ah[im][1], ah[im][2], ah[im][3],
                             bh[in][0], bh[in][1]);
                    MMA_BF16(acc[im][in][0], acc[im][in][1],
                             acc[im][in][2], acc[im][in][3],
                             ah[im][0], ah[im][1], ah[im][2], ah[im][3],
                             bl[in][0], bl[in][1]);
                    MMA_BF16(acc[im][in][0], acc[im][in][1],
                             acc[im][in][2], acc[im][in][3],
                             al[im][0], al[im][1], al[im][2], al[im][3],
                             bh[in][0], bh[in][1]);
                }
        }
        __syncthreads();
    }

    // ---- epilogue: warp covers 64 M rows (one output row), 32 co ----
    int h = h0 + strip_r;                // output row (unpadded)
    int cbase = 32*wn + 2*(lane & 3);
    #pragma unroll
    for (int im = 0; im < 4; ++im){
        #pragma unroll
        for (int in = 0; in < 4; ++in){
            int c0 = cbase + 8*in;
            float bia = s_bias[c0], bib = s_bias[c0+1];
            #pragma unroll
            for (int half = 0; half < 2; ++half){
                int px = 64*(wm & 1) + 16*im + (lane >> 2) + 8*half;
                float v0 = fmaxf(acc[im][in][2*half]   + bia, 0.f);
                float v1 = fmaxf(acc[im][in][2*half+1] + bib, 0.f);
                if (MODE == 0){
                    __nv_bfloat16 hh0 = __float2bfloat16(v0);
                    __nv_bfloat16 hh1 = __float2bfloat16(v1);
                    __nv_bfloat16 ll0 = __float2bfloat16(v0 - __bfloat162float(hh0));
                    __nv_bfloat16 ll1 = __float2bfloat16(v1 - __bfloat162float(hh1));
                    uint32_t hp = (uint32_t)__bfloat16_as_ushort(hh0) |
                                  ((uint32_t)__bfloat16_as_ushort(hh1) << 16);
                    uint32_t lp = (uint32_t)__bfloat16_as_ushort(ll0) |
                                  ((uint32_t)__bfloat16_as_ushort(ll1) << 16);
                    size_t e = (((size_t)b*HPAD + h + 1)*WPAD + (W0 + px + 1))*64 + c0;
                    *(uint32_t*)(out_h + e) = hp;
                    *(uint32_t*)(out_l + e) = lp;
                } else {
                    size_t e = ((size_t)(b*64 + c0)*HN + h)*WN + W0 + px;
                    out_f[e] = v0;
                    out_f[e + (size_t)HN*WN] = v1;
                }
            }
        }
    }
}

// ---------------- launch ----------------
extern "C" void kernel_launch(void* const* d_in, const int* in_sizes, int n_in,
                              void* d_out, int out_size)
{
    const float* points   = (const float*)d_in[0];
    const float* features = (const float*)d_in[1];
    const float* w1   = (const float*)d_in[2];
    const float* b1   = (const float*)d_in[3];
    const float* g1   = (const float*)d_in[4];
    const float* be1  = (const float*)d_in[5];
    const float* m1   = (const float*)d_in[6];
    const float* v1   = (const float*)d_in[7];
    const float* w2   = (const float*)d_in[8];
    const float* b2   = (const float*)d_in[9];
    const float* cw1  = (const float*)d_in[10];
    const float* cb1  = (const float*)d_in[11];
    const float* cg1  = (const float*)d_in[12];
    const float* cbe1 = (const float*)d_in[13];
    const float* cm1  = (const float*)d_in[14];
    const float* cv1  = (const float*)d_in[15];
    const float* cw2  = (const float*)d_in[16];
    const float* cb2  = (const float*)d_in[17];
    const float* cg2  = (const float*)d_in[18];
    const float* cbe2 = (const float*)d_in[19];
    const float* cm2  = (const float*)d_in[20];
    const float* cv2  = (const float*)d_in[21];
    float* out = (float*)d_out;

    void *p_c1h, *p_c1l, *p_c2h, *p_c2l;
    void *p_w1h, *p_w1l, *p_w2h, *p_w2l, *p_cb1, *p_cb2;
    cudaGetSymbolAddress(&p_c1h, g_c1h);
    cudaGetSymbolAddress(&p_c1l, g_c1l);
    cudaGetSymbolAddress(&p_c2h, g_c2h);
    cudaGetSymbolAddress(&p_c2l, g_c2l);
    cudaGetSymbolAddress(&p_w1h, g_cw1h);
    cudaGetSymbolAddress(&p_w1l, g_cw1l);
    cudaGetSymbolAddress(&p_w2h, g_cw2h);
    cudaGetSymbolAddress(&p_w2l, g_cw2l);
    cudaGetSymbolAddress(&p_cb1, g_cb1);
    cudaGetSymbolAddress(&p_cb2, g_cb2);

    cudaFuncSetAttribute(mlp_mma_kernel,
        cudaFuncAttributeMaxDynamicSharedMemorySize, MLP_SMEM_BYTES);
    cudaFuncSetAttribute(conv_mma_kernel<0>,
        cudaFuncAttributeMaxDynamicSharedMemorySize, CONV_SMEM_BYTES);
    cudaFuncSetAttribute(conv_mma_kernel<1>,
        cudaFuncAttributeMaxDynamicSharedMemorySize, CONV_SMEM_BYTES);

    // 1) zero BEV grid + fold weights (one launch)
    int prep_blocks = (PREP_TOTAL + 255)/256;
    init_kernel<<<ZBLOCKS + prep_blocks, 256>>>(
        w1,b1,g1,be1,m1,v1, w2,
        cw1,cb1,cg1,cbe1,cm1,cv1,
        cw2,cb2,cg2,cbe2,cm2,cv2);

    // 2) tensor-core point MLP + scatter-max (persistent)
    mlp_mma_kernel<<<296, 256, MLP_SMEM_BYTES>>>(points, features, b2);

    // 3) convert bev -> NHWC bf16 hi/lo
    bev2bf16_kernel<<<dim3(4, HN, BATCH), 256>>>();

    // 4) conv1 (mma.sync, 2-row tiles): g_c1 -> g_c2
    dim3 cgrid(2, HN/2, BATCH);
    conv_mma_kernel<0><<<cgrid, 256, CONV_SMEM_BYTES>>>(
        (const __nv_bfloat16*)p_c1h, (const __nv_bfloat16*)p_c1l,
        (const __nv_bfloat16*)p_w1h, (const __nv_bfloat16*)p_w1l,
        (const float*)p_cb1,
        (__nv_bfloat16*)p_c2h, (__nv_bfloat16*)p_c2l, nullptr);

    // 5) conv2 (mma.sync, 2-row tiles): g_c2 -> d_out (NCHW fp32)
    conv_mma_kernel<1><<<cgrid, 256, CONV_SMEM_BYTES>>>(
        (const __nv_bfloat16*)p_c2h, (const __nv_bfloat16*)p_c2l,
        (const __nv_bfloat16*)p_w2h, (const __nv_bfloat16*)p_w2l,
        (const float*)p_cb2,
        nullptr, nullptr, out);
}

// round 10
// speedup vs baseline: 1.0261x; 1.0261x over previous
#include <cuda_runtime.h>
#include <cuda_bf16.h>
#include <cstdint>

// ---------------- constants ----------------
#define HN     256
#define WN     256
#define HPAD   258
#define WPAD   258
#define NPTS   100000
#define BATCH  4
#define TOTPTS 400000
#define PLANE_PAD (HPAD*WPAD)                        // 66564
#define GRID_ELEMS ((size_t)BATCH*64*HPAD*WPAD)      // 17,040,384

// ---------------- device scratch ----------------
__device__ float g_bev[GRID_ELEMS];                  // fp32 NCHW padded (scatter target)
__device__ __nv_bfloat16 g_c1h[GRID_ELEMS];          // conv1 input NHWC padded, hi
__device__ __nv_bfloat16 g_c1l[GRID_ELEMS];          // lo
__device__ __nv_bfloat16 g_c2h[GRID_ELEMS];          // conv2 input NHWC padded, hi
__device__ __nv_bfloat16 g_c2l[GRID_ELEMS];          // lo
__device__ __nv_bfloat16 g_cw1h[9*64*64];            // [tap][co][ci] bf16 hi, BN-folded
__device__ __nv_bfloat16 g_cw1l[9*64*64];
__device__ __nv_bfloat16 g_cw2h[9*64*64];
__device__ __nv_bfloat16 g_cw2l[9*64*64];
__device__ __nv_bfloat16 g_mw1h[2*64*64];            // MLP L1 W [panel][co][k] hi (k<128)
__device__ __nv_bfloat16 g_mw1l[2*64*64];
__device__ __nv_bfloat16 g_mw2h[64*64];              // MLP L2 W [co][c]
__device__ __nv_bfloat16 g_mw2l[64*64];
__device__ float g_w1p[3*64];                        // pos rows of W1 (BN-folded, fp32)
__device__ float g_fb1[64];
__device__ float g_cb1[64];
__device__ float g_cb2[64];

// ---------------- mma / ldmatrix / cp.async / f32x2 helpers ----------------
__device__ __forceinline__ uint32_t smem_u32(const void* p){
    uint32_t a;
    asm("{ .reg .u64 t; cvta.to.shared.u64 t, %1; cvt.u32.u64 %0, t; }"
        : "=r"(a) : "l"(p));
    return a;
}
__device__ __forceinline__ unsigned long long PACK2F(float x, float y){
    unsigned long long r;
    asm("mov.b64 %0, {%1, %2};" : "=l"(r) : "f"(x), "f"(y));
    return r;
}
__device__ __forceinline__ unsigned long long PACK2U(uint32_t x, uint32_t y){
    unsigned long long r;
    asm("mov.b64 %0, {%1, %2};" : "=l"(r) : "r"(x), "r"(y));
    return r;
}
#define FMA2_3(d, a, b, c) asm("fma.rn.f32x2 %0, %1, %2, %3;" \
    : "=l"(d) : "l"(a), "l"(b), "l"(c))
#define LDSM_X4(r0,r1,r2,r3,addr) asm volatile( \
    "ldmatrix.sync.aligned.m8n8.x4.shared.b16 {%0,%1,%2,%3}, [%4];" \
    : "=r"(r0), "=r"(r1), "=r"(r2), "=r"(r3) : "r"(addr))
#define LDSM_X2(r0,r1,addr) asm volatile( \
    "ldmatrix.sync.aligned.m8n8.x2.shared.b16 {%0,%1}, [%2];" \
    : "=r"(r0), "=r"(r1) : "r"(addr))
#define MMA_BF16(c0,c1,c2,c3,a0,a1,a2,a3,b0,b1) asm volatile( \
    "mma.sync.aligned.m16n8k16.row.col.f32.bf16.bf16.f32 " \
    "{%0,%1,%2,%3}, {%4,%5,%6,%7}, {%8,%9}, {%0,%1,%2,%3};" \
    : "+f"(c0), "+f"(c1), "+f"(c2), "+f"(c3) \
    : "r"(a0), "r"(a1), "r"(a2), "r"(a3), "r"(b0), "r"(b1))
#define CP16(dst, src) asm volatile( \
    "cp.async.cg.shared.global [%0], [%1], 16;" :: "r"(dst), "l"(src))
#define CP_COMMIT() asm volatile("cp.async.commit_group;" ::: "memory")
#define CP_WAIT(n)  asm volatile("cp.async.wait_group %0;" :: "n"(n) : "memory")

// ---------------- init: zero BEV grid + fold weights (one launch) ----------------
#define ZBLOCKS 16641    // ceil(GRID_ELEMS/4 / 256)
#define PREP_TOTAL (8192 + 4096 + 192 + 64 + 2*9*64*64 + 2*64)

__global__ void init_kernel(
    const float* __restrict__ w1, const float* __restrict__ b1,
    const float* __restrict__ g1, const float* __restrict__ be1,
    const float* __restrict__ m1, const float* __restrict__ v1,
    const float* __restrict__ w2,
    const float* __restrict__ cw1, const float* __restrict__ cb1,
    const float* __restrict__ cg1, const float* __restrict__ cbe1,
    const float* __restrict__ cm1, const float* __restrict__ cv1,
    const float* __restrict__ cw2, const float* __restrict__ cb2,
    const float* __restrict__ cg2, const float* __restrict__ cbe2,
    const float* __restrict__ cm2, const float* __restrict__ cv2)
{
    if (blockIdx.x < ZBLOCKS){
        size_t i = (size_t)blockIdx.x*256 + threadIdx.x;
        if (i < GRID_ELEMS/4)
            ((float4*)g_bev)[i] = make_float4(0.f,0.f,0.f,0.f);
        return;
    }
    int idx = (blockIdx.x - ZBLOCKS)*256 + threadIdx.x;
    if (idx >= PREP_TOTAL) return;
    if (idx < 8192){                      // MLP W1 k<128: [panel][co][kk]
        int p = idx >> 12, r = idx & 4095, co = r >> 6, kk = r & 63;
        int k = p*64 + kk;
        float s = g1[co]*rsqrtf(v1[co]+1e-5f);
        float wf = w1[k*64+co]*s;
        __nv_bfloat16 hi = __float2bfloat16(wf);
        g_mw1h[idx] = hi;
        g_mw1l[idx] = __float2bfloat16(wf - __bfloat162float(hi));
        return;
    }
    idx -= 8192;
    if (idx < 4096){                      // MLP W2: [co][c]
        int co = idx >> 6, c = idx & 63;
        float wf = w2[c*64+co];
        __nv_bfloat16 hi = __float2bfloat16(wf);
        g_mw2h[idx] = hi;
        g_mw2l[idx] = __float2bfloat16(wf - __bfloat162float(hi));
        return;
    }
    idx -= 4096;
    if (idx < 192){                       // pos rows of W1, fp32
        int i = idx >> 6, co = idx & 63;
        float s = g1[co]*rsqrtf(v1[co]+1e-5f);
        g_w1p[idx] = w1[(128+i)*64+co]*s;
        return;
    }
    idx -= 192;
    if (idx < 64){
        float s = g1[idx]*rsqrtf(v1[idx]+1e-5f);
        g_fb1[idx] = (b1[idx]-m1[idx])*s + be1[idx];
        return;
    }
    idx -= 64;
    if (idx < 9*64*64){
        int t = idx >> 12, co = (idx >> 6) & 63, ci = idx & 63;
        float s = cg1[co]*rsqrtf(cv1[co]+1e-5f);
        float wf = cw1[(co*64+ci)*9 + t]*s;
        __nv_bfloat16 hi = __float2bfloat16(wf);
        g_cw1h[idx] = hi;
        g_cw1l[idx] = __float2bfloat16(wf - __bfloat162float(hi));
        return;
    }
    idx -= 9*64*64;
    if (idx < 9*64*64){
        int t = idx >> 12, co = (idx >> 6) & 63, ci = idx & 63;
        float s = cg2[co]*rsqrtf(cv2[co]+1e-5f);
        float wf = cw2[(co*64+ci)*9 + t]*s;
        __nv_bfloat16 hi = __float2bfloat16(wf);
        g_cw2h[idx] = hi;
        g_cw2l[idx] = __float2bfloat16(wf - __bfloat162float(hi));
        return;
    }
    idx -= 9*64*64;
    if (idx < 64){
        float s = cg1[idx]*rsqrtf(cv1[idx]+1e-5f);
        g_cb1[idx] = (cb1[idx]-cm1[idx])*s + cbe1[idx];
        return;
    }
    idx -= 64;
    if (idx < 64){
        float s = cg2[idx]*rsqrtf(cv2[idx]+1e-5f);
        g_cb2[idx] = (cb2[idx]-cm2[idx])*s + cbe2[idx];
    }
}

// ---------------- tensor-core MLP + scatter-max ----------------
#define MLPS_W1   0
#define MLPS_W2   32768
#define MLPS_A    49152
#define MLPS_HH   81920
#define MLPS_HL   90112
#define MLPS_W1P  98304
#define MLPS_FB1  99072
#define MLPS_B2   99328
#define MLPS_POS  99584
#define MLPS_INFO 100608
#define MLP_SMEM_BYTES 100864
#define NCHUNKS 6250

__global__ __launch_bounds__(256, 2)
void mlp_mma_kernel(const float* __restrict__ points,
                    const float* __restrict__ features,
                    const float* __restrict__ b2)
{
    extern __shared__ char smem[];
    uint32_t sb = smem_u32(smem);
    float* s_w1p = (float*)(smem + MLPS_W1P);
    float* s_fb1 = (float*)(smem + MLPS_FB1);
    float* s_b2  = (float*)(smem + MLPS_B2);
    float* s_pos = (float*)(smem + MLPS_POS);
    int*   s_info= (int*)(smem + MLPS_INFO);

    int tid = threadIdx.x;
    int lane = tid & 31;
    int wq = tid >> 5;
    int wm = wq & 3;
    int wn = wq >> 2;
    int tile = lane >> 3;
    int r16  = ((tile & 1) << 3) + (lane & 7);
    int kcA  = tile >> 1;
    int coL  = lane & 7;
    int kcB  = tile & 1;
    const unsigned long long neg1 = PACK2F(-1.f, -1.f);

    for (int j = tid; j < 2048; j += 256){
        int panel = j >> 9, r = (j >> 3) & 63, c = j & 7;
        const __nv_bfloat16* src = (panel < 2)
            ? (g_mw1h + panel*4096 + r*64 + c*8)
            : (g_mw1l + (panel-2)*4096 + r*64 + c*8);
        CP16(sb + MLPS_W1 + panel*8192 + r*128 + ((c ^ (r & 7)) << 4), src);
    }
    for (int j = tid; j < 1024; j += 256){
        int panel = j >> 9, r = (j >> 3) & 63, c = j & 7;
        const __nv_bfloat16* src = (panel ? g_mw2l : g_mw2h) + r*64 + c*8;
        CP16(sb + MLPS_W2 + panel*8192 + r*128 + ((c ^ (r & 7)) << 4), src);
    }
    CP_COMMIT();
    if (tid < 192) s_w1p[tid] = g_w1p[tid];
    if (tid < 64){ s_fb1[tid] = g_fb1[tid]; s_b2[tid] = b2[tid]; }
    CP_WAIT(0);
    __syncthreads();

    for (int chunk = blockIdx.x; chunk < NCHUNKS; chunk += gridDim.x){
        int g0 = chunk * 64;

        // ---- stage A: fp32 -> bf16 hi/lo; lo residual via packed fma.rn.f32x2 ----
        #pragma unroll
        for (int i = 0; i < 4; ++i){
            int j = tid + i*256;
            int pt = j >> 4, oct = j & 15;
            const uint4* src = (const uint4*)(features + (size_t)(g0+pt)*128 + oct*8);
            uint4 u0 = src[0], u1 = src[1];
            uint4 hv, lv;
            hv.x = __byte_perm(u0.x, u0.y, 0x7632);
            hv.y = __byte_perm(u0.z, u0.w, 0x7632);
            hv.z = __byte_perm(u1.x, u1.y, 0x7632);
            hv.w = __byte_perm(u1.z, u1.w, 0x7632);
            unsigned long long m, xx, l;
            m  = PACK2U(u0.x & 0xFFFF0000u, u0.y & 0xFFFF0000u);
            xx = PACK2U(u0.x, u0.y);
            FMA2_3(l, m, neg1, xx);
            lv.x = __byte_perm((uint32_t)l, (uint32_t)(l >> 32), 0x7632);
            m  = PACK2U(u0.z & 0xFFFF0000u, u0.w & 0xFFFF0000u);
            xx = PACK2U(u0.z, u0.w);
            FMA2_3(l, m, neg1, xx);
            lv.y = __byte_perm((uint32_t)l, (uint32_t)(l >> 32), 0x7632);
            m  = PACK2U(u1.x & 0xFFFF0000u, u1.y & 0xFFFF0000u);
            xx = PACK2U(u1.x, u1.y);
            FMA2_3(l, m, neg1, xx);
            lv.z = __byte_perm((uint32_t)l, (uint32_t)(l >> 32), 0x7632);
            m  = PACK2U(u1.z & 0xFFFF0000u, u1.w & 0xFFFF0000u);
            xx = PACK2U(u1.z, u1.w);
            FMA2_3(l, m, neg1, xx);
            lv.w = __byte_perm((uint32_t)l, (uint32_t)(l >> 32), 0x7632);
            int panel = oct >> 3, c = oct & 7;
            uint32_t off = MLPS_A + panel*8192 + pt*128 + ((c ^ (pt & 7)) << 4);
            *(uint4*)(smem + off) = hv;
            *(uint4*)(smem + off + 16384) = lv;
        }
        if (tid < 64){
            int g = g0 + tid;
            float x = points[(size_t)g*3+0];
            float y = points[(size_t)g*3+1];
            float z = points[(size_t)g*3+2];
            bool valid = (x >= -50.f) && (x < 50.f) && (y >= -50.f) &&
                         (y < 50.f) && (z >= -3.f) && (z < 5.f);
            s_pos[tid*4+0] = __fdiv_rn(x + 50.f, 100.f);
            s_pos[tid*4+1] = __fdiv_rn(y + 50.f, 100.f);
            s_pos[tid*4+2] = __fdiv_rn(z + 3.f, 8.f);
            int info = -1;
            if (valid){
                int col = (int)__fdiv_rn(x + 50.f, 0.390625f);
                int row = (int)__fdiv_rn(y + 50.f, 0.390625f);
                col = min(max(col,0),255); row = min(max(row,0),255);
                int b = g / NPTS;
                info = (b<<18) | (row<<9) | col;
            }
            s_info[tid] = info;
        }
        __syncthreads();

        // ---- layer 1 GEMM ----
        float acc[4][4];
        #pragma unroll
        for (int in = 0; in < 4; ++in)
            #pragma unroll
            for (int r = 0; r < 4; ++r) acc[in][r] = 0.f;

        int arow = 16*wm + r16;
        #pragma unroll
        for (int ks = 0; ks < 8; ++ks){
            int panel = ks >> 2, cc = 2*(ks & 3);
            uint32_t ah[4], al[4], bh[4][2], bl[4][2];
            uint32_t aad = sb + MLPS_A + panel*8192 + arow*128
                         + (((cc + kcA) ^ (arow & 7)) << 4);
            LDSM_X4(ah[0], ah[1], ah[2], ah[3], aad);
            LDSM_X4(al[0], al[1], al[2], al[3], aad + 16384);
            #pragma unroll
            for (int in = 0; in < 4; ++in){
                int co = 32*wn + 8*in + coL;
                uint32_t bad = sb + MLPS_W1 + panel*8192 + co*128
                             + (((cc + kcB) ^ (co & 7)) << 4);
                LDSM_X2(bh[in][0], bh[in][1], bad);
                LDSM_X2(bl[in][0], bl[in][1], bad + 16384);
            }
            #pragma unroll
            for (int in = 0; in < 4; ++in){
                MMA_BF16(acc[in][0],acc[in][1],acc[in][2],acc[in][3],
                         ah[0],ah[1],ah[2],ah[3], bh[in][0],bh[in][1]);
                MMA_BF16(acc[in][0],acc[in][1],acc[in][2],acc[in][3],
                         ah[0],ah[1],ah[2],ah[3], bl[in][0],bl[in][1]);
                MMA_BF16(acc[in][0],acc[in][1],acc[in][2],acc[in][3],
                         al[0],al[1],al[2],al[3], bh[in][0],bh[in][1]);
            }
        }

        // ---- epilogue 1: + pos (fp32) + bias, ReLU, rn-split -> H ----
        int rb = 16*wm + (lane >> 2);
        int cb = 2*(lane & 3);
        #pragma unroll
        for (int in = 0; in < 4; ++in){
            int c0 = 32*wn + 8*in + cb;
            float p0a = s_w1p[c0],      p0b = s_w1p[c0+1];
            float p1a = s_w1p[64+c0],   p1b = s_w1p[64+c0+1];
            float p2a = s_w1p[128+c0],  p2b = s_w1p[128+c0+1];
            float fba = s_fb1[c0], fbb = s_fb1[c0+1];
            int ch = c0 >> 3;
            #pragma unroll
            for (int half = 0; half < 2; ++half){
                int pt = rb + 8*half;
                float px = s_pos[pt*4], py = s_pos[pt*4+1], pz = s_pos[pt*4+2];
                float v0 = acc[in][2*half]   + fba + px*p0a + py*p1a + pz*p2a;
                float v1 = acc[in][2*half+1] + fbb + px*p0b + py*p1b + pz*p2b;
                v0 = fmaxf(v0, 0.f); v1 = fmaxf(v1, 0.f);
                __nv_bfloat16 h0 = __float2bfloat16(v0);
                __nv_bfloat16 h1 = __float2bfloat16(v1);
                __nv_bfloat16 q0 = __float2bfloat16(v0 - __bfloat162float(h0));
                __nv_bfloat16 q1 = __float2bfloat16(v1 - __bfloat162float(h1));
                uint32_t hp = (uint32_t)__bfloat16_as_ushort(h0) |
                              ((uint32_t)__bfloat16_as_ushort(h1) << 16);
                uint32_t lp = (uint32_t)__bfloat16_as_ushort(q0) |
                              ((uint32_t)__bfloat16_as_ushort(q1) << 16);
                uint32_t off = pt*128 + ((ch ^ (pt & 7)) << 4) + cb*2;
                *(uint32_t*)(smem + MLPS_HH + off) = hp;
                *(uint32_t*)(smem + MLPS_HL + off) = lp;
            }
        }
        __syncthreads();

        // ---- layer 2 GEMM ----
        float acc2[4][4];
        #pragma unroll
        for (int in = 0; in < 4; ++in)
            #pragma unroll
            for (int r = 0; r < 4; ++r) acc2[in][r] = 0.f;

        #pragma unroll
        for (int ks = 0; ks < 4; ++ks){
            int cc = 2*ks;
            uint32_t ah[4], al[4], bh[4][2], bl[4][2];
            uint32_t aad = sb + MLPS_HH + arow*128
                         + (((cc + kcA) ^ (arow & 7)) << 4);
            LDSM_X4(ah[0], ah[1], ah[2], ah[3], aad);
            LDSM_X4(al[0], al[1], al[2], al[3], aad + 8192);
            #pragma unroll
            for (int in = 0; in < 4; ++in){
                int co = 32*wn + 8*in + coL;
                uint32_t bad = sb + MLPS_W2 + co*128
                             + (((cc + kcB) ^ (co & 7)) << 4);
                LDSM_X2(bh[in][0], bh[in][1], bad);
                LDSM_X2(bl[in][0], bl[in][1], bad + 8192);
            }
            #pragma unroll
            for (int in = 0; in < 4; ++in){
                MMA_BF16(acc2[in][0],acc2[in][1],acc2[in][2],acc2[in][3],
                         ah[0],ah[1],ah[2],ah[3], bh[in][0],bh[in][1]);
                MMA_BF16(acc2[in][0],acc2[in][1],acc2[in][2],acc2[in][3],
                         ah[0],ah[1],ah[2],ah[3], bl[in][0],bl[in][1]);
                MMA_BF16(acc2[in][0],acc2[in][1],acc2[in][2],acc2[in][3],
                         al[0],al[1],al[2],al[3], bh[in][0],bh[in][1]);
            }
        }

        // ---- epilogue 2: + b2, scatter-max ----
        #pragma unroll
        for (int in = 0; in < 4; ++in){
            int c0 = 32*wn + 8*in + cb;
            float bb0 = s_b2[c0], bb1 = s_b2[c0+1];
            #pragma unroll
            for (int half = 0; half < 2; ++half){
                int pt = rb + 8*half;
                int info = s_info[pt];
                if (info < 0) continue;
                int b   = info >> 18;
                int row = (info >> 9) & 511;
                int col = info & 511;
                float v0 = acc2[in][2*half]   + bb0;
                float v1 = acc2[in][2*half+1] + bb1;
                size_t obase = ((size_t)(b*64 + c0)*HPAD + row + 1)*WPAD + col + 1;
                if (v0 > 0.f)
                    atomicMax((unsigned int*)&g_bev[obase], __float_as_uint(v0));
                if (v1 > 0.f)
                    atomicMax((unsigned int*)&g_bev[obase + PLANE_PAD],
                              __float_as_uint(v1));
            }
        }
        __syncthreads();
    }
}

// ---------------- bev fp32 NCHW -> NHWC bf16 hi/lo ----------------
__global__ __launch_bounds__(256)
void bev2bf16_kernel(){
    __shared__ float ts[64*65];
    int b = blockIdx.z, h = blockIdx.y, w0 = blockIdx.x*64;
    int tid = threadIdx.x;
    #pragma unroll
    for (int i = 0; i < 16; ++i){
        int idx = tid + i*256;
        int ch = idx >> 6, px = idx & 63;
        ts[ch*65 + px] = g_bev[(size_t)(b*64+ch)*PLANE_PAD
                               + (size_t)(h+1)*WPAD + (w0+1+px)];
    }
    __syncthreads();
    int px = tid >> 2, cq = (tid & 3) * 16;
    size_t base = (((size_t)b*HPAD + h + 1)*WPAD + (w0+1+px))*64 + cq;
    uint32_t hp[8], lp[8];
    #pragma unroll
    for (int j = 0; j < 8; ++j){
        float v0 = ts[(cq+2*j)*65 + px];
        float v1 = ts[(cq+2*j+1)*65 + px];
        __nv_bfloat16 h0 = __float2bfloat16(v0);
        __nv_bfloat16 h1 = __float2bfloat16(v1);
        __nv_bfloat16 l0 = __float2bfloat16(v0 - __bfloat162float(h0));
        __nv_bfloat16 l1 = __float2bfloat16(v1 - __bfloat162float(h1));
        hp[j] = (uint32_t)__bfloat16_as_ushort(h0) |
                ((uint32_t)__bfloat16_as_ushort(h1) << 16);
        lp[j] = (uint32_t)__bfloat16_as_ushort(l0) |
                ((uint32_t)__bfloat16_as_ushort(l1) << 16);
    }
    *(uint4*)(g_c1h + base)     = *(uint4*)&hp[0];
    *(uint4*)(g_c1h + base + 8) = *(uint4*)&hp[4];
    *(uint4*)(g_c1l + base)     = *(uint4*)&lp[0];
    *(uint4*)(g_c1l + base + 8) = *(uint4*)&lp[4];
}

// ---------------- tensor-core conv via mma.sync bf16 (R7 tile, proven) ----------------
#define SA_BUF   33280
#define SW_OFF   (2*SA_BUF)            // 66560
#define SW_BUF   16384
#define SBIAS    (SW_OFF + 2*SW_BUF)   // 99328
#define CONV_SMEM_BYTES (SBIAS + 256)  // 99584

template<int MODE>
__global__ __launch_bounds__(256, 2)
void conv_mma_kernel(const __nv_bfloat16* __restrict__ in_h,
                     const __nv_bfloat16* __restrict__ in_l,
                     const __nv_bfloat16* __restrict__ w_h,
                     const __nv_bfloat16* __restrict__ w_l,
                     const float* __restrict__ bias,
                     __nv_bfloat16* __restrict__ out_h,
                     __nv_bfloat16* __restrict__ out_l,
                     float* __restrict__ out_f)
{
    extern __shared__ char smem[];
    uint32_t sbase = smem_u32(smem);
    float* s_bias = (float*)(smem + SBIAS);

    int tid = threadIdx.x;
    int lane = tid & 31;
    int wq = tid >> 5;
    int wm = wq & 3;
    int wn = wq >> 2;
    int b = blockIdx.z, h = blockIdx.y, W0 = blockIdx.x * 128;

    if (tid < 64) s_bias[tid] = bias[tid];

    int tile = lane >> 3;
    int r16  = ((tile & 1) << 3) + (lane & 7);
    int kcA  = tile >> 1;
    int coL  = (lane & 7);
    int kcB  = tile & 1;

    auto stage_strip = [&](int dh, int buf){
        const char* srch = (const char*)(in_h +
            (((size_t)b*HPAD + h + dh)*WPAD + W0)*64);
        const char* srcl = (const char*)(in_l +
            (((size_t)b*HPAD + h + dh)*WPAD + W0)*64);
        uint32_t dsth = sbase + buf*SA_BUF;
        uint32_t dstl = dsth + 16640;
        #pragma unroll 1
        for (int ch = tid; ch < 1040; ch += 256){
            int px = ch >> 3, c = ch & 7;
            uint32_t off = px*128 + ((c ^ (px & 7)) << 4);
            CP16(dsth + off, srch + ch*16);
            CP16(dstl + off, srcl + ch*16);
        }
    };
    auto stage_w = [&](int t, int buf){
        const char* srch = (const char*)(w_h + t*4096);
        const char* srcl = (const char*)(w_l + t*4096);
        uint32_t dsth = sbase + SW_OFF + buf*SW_BUF;
        uint32_t dstl = dsth + 8192;
        #pragma unroll 1
        for (int ch = tid; ch < 512; ch += 256){
            int co = ch >> 3, c = ch & 7;
            uint32_t off = co*128 + ((c ^ (co & 7)) << 4);
            CP16(dsth + off, srch + ch*16);
            CP16(dstl + off, srcl + ch*16);
        }
    };

    float acc[2][4][4];
    #pragma unroll
    for (int im = 0; im < 2; ++im)
        #pragma unroll
        for (int in = 0; in < 4; ++in)
            #pragma unroll
            for (int r = 0; r < 4; ++r) acc[im][in][r] = 0.f;

    stage_strip(0, 0);
    stage_w(0, 0);
    CP_COMMIT();

    #pragma unroll 1
    for (int t = 0; t < 9; ++t){
        int dh = t / 3, dw = t - dh*3;
        if (t < 8){
            stage_w(t+1, (t+1) & 1);
            if ((t+1) % 3 == 0) stage_strip((t+1)/3, ((t+1)/3) & 1);
            CP_COMMIT();
            CP_WAIT(1);
        } else {
            CP_WAIT(0);
        }
        __syncthreads();

        uint32_t Ah = sbase + (dh & 1)*SA_BUF;
        uint32_t Al = Ah + 16640;
        uint32_t Wh = sbase + SW_OFF + (t & 1)*SW_BUF;
        uint32_t Wl = Wh + 8192;

        #pragma unroll
        for (int ks = 0; ks < 4; ++ks){
            uint32_t ah[2][4], al[2][4], bh[4][2], bl[4][2];
            #pragma unroll
            for (int im = 0; im < 2; ++im){
                int px = dw + 32*wm + 16*im + r16;
                int chunk = 2*ks + kcA;
                uint32_t ad = Ah + px*128 + ((chunk ^ (px & 7)) << 4);
                LDSM_X4(ah[im][0], ah[im][1], ah[im][2], ah[im][3], ad);
            }
            #pragma unroll
            for (int in = 0; in < 4; ++in){
                int co = 32*wn + 8*in + coL;
                int chunk = 2*ks + kcB;
                uint32_t bd = Wh + co*128 + ((chunk ^ (co & 7)) << 4);
                LDSM_X2(bh[in][0], bh[in][1], bd);
            }
            #pragma unroll
            for (int im = 0; im < 2; ++im)
                #pragma unroll
                for (int in = 0; in < 4; ++in)
                    MMA_BF16(acc[im][in][0], acc[im][in][1],
                             acc[im][in][2], acc[im][in][3],
                             ah[im][0], ah[im][1], ah[im][2], ah[im][3],
                             bh[in][0], bh[in][1]);
            #pragma unroll
            for (int in = 0; in < 4; ++in){
                int co = 32*wn + 8*in + coL;
                int chunk = 2*ks + kcB;
                uint32_t bd = Wl + co*128 + ((chunk ^ (co & 7)) << 4);
                LDSM_X2(bl[in][0], bl[in][1], bd);
            }
            #pragma unroll
            for (int im = 0; im < 2; ++im)
                #pragma unroll
                for (int in = 0; in < 4; ++in)
                    MMA_BF16(acc[im][in][0], acc[im][in][1],
                             acc[im][in][2], acc[im][in][3],
                             ah[im][0], ah[im][1], ah[im][2], ah[im][3],
                             bl[in][0], bl[in][1]);
            #pragma unroll
            for (int im = 0; im < 2; ++im){
                int px = dw + 32*wm + 16*im + r16;
                int chunk = 2*ks + kcA;
                uint32_t ad = Al + px*128 + ((chunk ^ (px & 7)) << 4);
                LDSM_X4(al[im][0], al[im][1], al[im][2], al[im][3], ad);
            }
            #pragma unroll
            for (int im = 0; im < 2; ++im)
                #pragma unroll
                for (int in = 0; in < 4; ++in)
                    MMA_BF16(acc[im][in][0], acc[im][in][1],
                             acc[im][in][2], acc[im][in][3],
                             al[im][0], al[im][1], al[im][2], al[im][3],
                             bh[in][0], bh[in][1]);
        }
        __syncthreads();
    }

    int rbase = 32*wm + (lane >> 2);
    int cbase = 32*wn + 2*(lane & 3);
    #pragma unroll
    for (int im = 0; im < 2; ++im){
        #pragma unroll
        for (int in = 0; in < 4; ++in){
            int c0 = cbase + 8*in;
            float bia = s_bias[c0], bib = s_bias[c0+1];
            #pragma unroll
            for (int half = 0; half < 2; ++half){
                int px = rbase + 16*im + 8*half;
                float v0 = fmaxf(acc[im][in][2*half]   + bia, 0.f);
                float v1 = fmaxf(acc[im][in][2*half+1] + bib, 0.f);
                if (MODE == 0){
                    __nv_bfloat16 h0 = __float2bfloat16(v0);
                    __nv_bfloat16 h1 = __float2bfloat16(v1);
                    __nv_bfloat16 l0 = __float2bfloat16(v0 - __bfloat162float(h0));
                    __nv_bfloat16 l1 = __float2bfloat16(v1 - __bfloat162float(h1));
                    uint32_t hp = (uint32_t)__bfloat16_as_ushort(h0) |
                                  ((uint32_t)__bfloat16_as_ushort(h1) << 16);
                    uint32_t lp = (uint32_t)__bfloat16_as_ushort(l0) |
                                  ((uint32_t)__bfloat16_as_ushort(l1) << 16);
                    size_t e = (((size_t)b*HPAD + h + 1)*WPAD + (W0 + px + 1))*64 + c0;
                    *(uint32_t*)(out_h + e) = hp;
                    *(uint32_t*)(out_l + e) = lp;
                } else {
                    size_t e = ((size_t)(b*64 + c0)*HN + h)*WN + W0 + px;
                    out_f[e] = v0;
                    out_f[e + (size_t)HN*WN] = v1;
                }
            }
        }
    }
}

// ---------------- launch ----------------
extern "C" void kernel_launch(void* const* d_in, const int* in_sizes, int n_in,
                              void* d_out, int out_size)
{
    const float* points   = (const float*)d_in[0];
    const float* features = (const float*)d_in[1];
    const float* w1   = (const float*)d_in[2];
    const float* b1   = (const float*)d_in[3];
    const float* g1   = (const float*)d_in[4];
    const float* be1  = (const float*)d_in[5];
    const float* m1   = (const float*)d_in[6];
    const float* v1   = (const float*)d_in[7];
    const float* w2   = (const float*)d_in[8];
    const float* b2   = (const float*)d_in[9];
    const float* cw1  = (const float*)d_in[10];
    const float* cb1  = (const float*)d_in[11];
    const float* cg1  = (const float*)d_in[12];
    const float* cbe1 = (const float*)d_in[13];
    const float* cm1  = (const float*)d_in[14];
    const float* cv1  = (const float*)d_in[15];
    const float* cw2  = (const float*)d_in[16];
    const float* cb2  = (const float*)d_in[17];
    const float* cg2  = (const float*)d_in[18];
    const float* cbe2 = (const float*)d_in[19];
    const float* cm2  = (const float*)d_in[20];
    const float* cv2  = (const float*)d_in[21];
    float* out = (float*)d_out;

    void *p_c1h, *p_c1l, *p_c2h, *p_c2l;
    void *p_w1h, *p_w1l, *p_w2h, *p_w2l, *p_cb1, *p_cb2;
    cudaGetSymbolAddress(&p_c1h, g_c1h);
    cudaGetSymbolAddress(&p_c1l, g_c1l);
    cudaGetSymbolAddress(&p_c2h, g_c2h);
    cudaGetSymbolAddress(&p_c2l, g_c2l);
    cudaGetSymbolAddress(&p_w1h, g_cw1h);
    cudaGetSymbolAddress(&p_w1l, g_cw1l);
    cudaGetSymbolAddress(&p_w2h, g_cw2h);
    cudaGetSymbolAddress(&p_w2l, g_cw2l);
    cudaGetSymbolAddress(&p_cb1, g_cb1);
    cudaGetSymbolAddress(&p_cb2, g_cb2);

    cudaFuncSetAttribute(mlp_mma_kernel,
        cudaFuncAttributeMaxDynamicSharedMemorySize, MLP_SMEM_BYTES);
    cudaFuncSetAttribute(conv_mma_kernel<0>,
        cudaFuncAttributeMaxDynamicSharedMemorySize, CONV_SMEM_BYTES);
    cudaFuncSetAttribute(conv_mma_kernel<1>,
        cudaFuncAttributeMaxDynamicSharedMemorySize, CONV_SMEM_BYTES);

    // 1) zero BEV grid + fold weights (one launch)
    int prep_blocks = (PREP_TOTAL + 255)/256;
    init_kernel<<<ZBLOCKS + prep_blocks, 256>>>(
        w1,b1,g1,be1,m1,v1, w2,
        cw1,cb1,cg1,cbe1,cm1,cv1,
        cw2,cb2,cg2,cbe2,cm2,cv2);

    // 2) tensor-core point MLP + scatter-max (persistent)
    mlp_mma_kernel<<<296, 256, MLP_SMEM_BYTES>>>(points, features, b2);

    // 3) convert bev -> NHWC bf16 hi/lo
    bev2bf16_kernel<<<dim3(4, HN, BATCH), 256>>>();

    // 4) conv1 (mma.sync, R7 tile): g_c1 -> g_c2
    dim3 cgrid(2, HN, BATCH);
    conv_mma_kernel<0><<<cgrid, 256, CONV_SMEM_BYTES>>>(
        (const __nv_bfloat16*)p_c1h, (const __nv_bfloat16*)p_c1l,
        (const __nv_bfloat16*)p_w1h, (const __nv_bfloat16*)p_w1l,
        (const float*)p_cb1,
        (__nv_bfloat16*)p_c2h, (__nv_bfloat16*)p_c2l, nullptr);

    // 5) conv2 (mma.sync, R7 tile): g_c2 -> d_out (NCHW fp32)
    conv_mma_kernel<1><<<cgrid, 256, CONV_SMEM_BYTES>>>(
        (const __nv_bfloat16*)p_c2h, (const __nv_bfloat16*)p_c2l,
        (const __nv_bfloat16*)p_w2h, (const __nv_bfloat16*)p_w2l,
        (const float*)p_cb2,
        nullptr, nullptr, out);
}